// round 1
// baseline (speedup 1.0000x reference)
#include <cuda_runtime.h>
#include <cuda_bf16.h>
#include <math.h>

// Problem constants (fixed by setup_inputs: S=2048, U=10, D=256)
#define B_TOT 20480
#define D_DIM 256
#define S_CLS 2048
#define U_UTT 10
#define EPSF  1e-8f

// Scratch (static __device__ arrays: allocation-free per harness rules)
__device__ float g_En[(size_t)B_TOT * D_DIM];   // normalized embeddings, 20 MB
__device__ float g_Cn[(size_t)S_CLS * D_DIM];   // normalized centroids, 2 MB
__device__ float g_rowsum[B_TOT];               // sum_k exp(sim[row,k])
__device__ float g_pos[B_TOT];                  // sim[row, label(row)]

// ---------------------------------------------------------------------------
// block-wide sum for blockDim.x == 256, result broadcast to all threads
// ---------------------------------------------------------------------------
__device__ __forceinline__ float blockReduce256(float v) {
    __shared__ float sh[8];
    int lane = threadIdx.x & 31;
    int w    = threadIdx.x >> 5;
    #pragma unroll
    for (int o = 16; o; o >>= 1) v += __shfl_xor_sync(0xffffffffu, v, o);
    if (lane == 0) sh[w] = v;
    __syncthreads();
    if (w == 0) {
        v = (lane < 8) ? sh[lane] : 0.0f;
        #pragma unroll
        for (int o = 4; o; o >>= 1) v += __shfl_xor_sync(0xffffffffu, v, o);
        if (lane == 0) sh[0] = v;
    }
    __syncthreads();
    return sh[0];
}

// ---------------------------------------------------------------------------
// Kernel 1: per-speaker centroid (mean over U) -> L2 normalize -> g_Cn
// grid = S_CLS, block = 256 (one thread per dim)
// ---------------------------------------------------------------------------
__global__ void centroid_kernel(const float* __restrict__ emb) {
    int s = blockIdx.x;
    int d = threadIdx.x;
    float c = 0.0f;
    #pragma unroll
    for (int u = 0; u < U_UTT; u++)
        c += emb[((size_t)(s * U_UTT + u)) * D_DIM + d];
    c *= (1.0f / U_UTT);
    float sq = blockReduce256(c * c);
    float norm = fmaxf(sqrtf(sq), EPSF);
    g_Cn[(size_t)s * D_DIM + d] = c / norm;
}

// ---------------------------------------------------------------------------
// Kernel 2: L2-normalize each embedding row -> g_En ; zero g_rowsum
// grid = B_TOT, block = 256
// ---------------------------------------------------------------------------
__global__ void normalize_kernel(const float* __restrict__ emb) {
    int row = blockIdx.x;
    int d   = threadIdx.x;
    float v = emb[(size_t)row * D_DIM + d];
    float sq = blockReduce256(v * v);
    float norm = fmaxf(sqrtf(sq), EPSF);
    g_En[(size_t)row * D_DIM + d] = v / norm;
    if (d == 0) g_rowsum[row] = 0.0f;
}

// ---------------------------------------------------------------------------
// Kernel 3: pos[row] = dot(En[row], Cn[row / U])
// grid = B_TOT, block = 256
// ---------------------------------------------------------------------------
__global__ void pos_kernel() {
    int row = blockIdx.x;
    int d   = threadIdx.x;
    int s   = row / U_UTT;
    float p = g_En[(size_t)row * D_DIM + d] * g_Cn[(size_t)s * D_DIM + d];
    p = blockReduce256(p);
    if (d == 0) g_pos[row] = p;
}

// ---------------------------------------------------------------------------
// Kernel 4: fused GEMM (En @ Cn^T) + exp + row-sum accumulate.
// 128x128 output tile, BK=16, double-buffered smem, 8x8 register micro-tile,
// 256 threads, 2 blocks/SM. rowsum accumulated via one atomicAdd per row/block.
// No max-subtraction needed: |sim| <= 1 so exp(sim) in [1/e, e].
// ---------------------------------------------------------------------------
#define BM 128
#define BN 128
#define BK 16
#define NKC (D_DIM / BK)   // 16 k-chunks

__global__ __launch_bounds__(256, 2)
void gemm_exp_kernel() {
    __shared__ float As[2][BK][BM];
    __shared__ float Bs[2][BK][BN];

    const int rowTile = blockIdx.x * BM;
    const int colTile = blockIdx.y * BN;
    const int tid = threadIdx.x;
    const int tx  = tid & 15;   // 0..15 -> output cols
    const int ty  = tid >> 4;   // 0..15 -> output rows

    // Load mapping: 512 float4 per operand tile, 2 per thread.
    const int lRow  = tid >> 2;        // 0..63
    const int lQuad = tid & 3;         // 0..3 -> k offsets quad*4 .. quad*4+3

    const float* Aptr0 = g_En + (size_t)(rowTile + lRow)      * D_DIM + lQuad * 4;
    const float* Aptr1 = g_En + (size_t)(rowTile + lRow + 64) * D_DIM + lQuad * 4;
    const float* Bptr0 = g_Cn + (size_t)(colTile + lRow)      * D_DIM + lQuad * 4;
    const float* Bptr1 = g_Cn + (size_t)(colTile + lRow + 64) * D_DIM + lQuad * 4;

    float acc[8][8];
    #pragma unroll
    for (int i = 0; i < 8; i++)
        #pragma unroll
        for (int j = 0; j < 8; j++) acc[i][j] = 0.0f;

    // ---- tile loader (global -> smem, transposed to k-major) ----
    auto loadTile = [&](int kc, int buf) {
        int kb = kc * BK;
        float4 a0 = *(const float4*)(Aptr0 + kb);
        float4 a1 = *(const float4*)(Aptr1 + kb);
        float4 b0 = *(const float4*)(Bptr0 + kb);
        float4 b1 = *(const float4*)(Bptr1 + kb);
        int k0 = lQuad * 4;
        As[buf][k0 + 0][lRow]      = a0.x;
        As[buf][k0 + 1][lRow]      = a0.y;
        As[buf][k0 + 2][lRow]      = a0.z;
        As[buf][k0 + 3][lRow]      = a0.w;
        As[buf][k0 + 0][lRow + 64] = a1.x;
        As[buf][k0 + 1][lRow + 64] = a1.y;
        As[buf][k0 + 2][lRow + 64] = a1.z;
        As[buf][k0 + 3][lRow + 64] = a1.w;
        Bs[buf][k0 + 0][lRow]      = b0.x;
        Bs[buf][k0 + 1][lRow]      = b0.y;
        Bs[buf][k0 + 2][lRow]      = b0.z;
        Bs[buf][k0 + 3][lRow]      = b0.w;
        Bs[buf][k0 + 0][lRow + 64] = b1.x;
        Bs[buf][k0 + 1][lRow + 64] = b1.y;
        Bs[buf][k0 + 2][lRow + 64] = b1.z;
        Bs[buf][k0 + 3][lRow + 64] = b1.w;
    };

    int buf = 0;
    loadTile(0, 0);
    __syncthreads();

    #pragma unroll 1
    for (int kc = 0; kc < NKC; kc++) {
        if (kc + 1 < NKC) loadTile(kc + 1, buf ^ 1);
        #pragma unroll
        for (int kk = 0; kk < BK; kk++) {
            float a[8], b[8];
            *(float4*)&a[0] = *(const float4*)&As[buf][kk][ty * 8];
            *(float4*)&a[4] = *(const float4*)&As[buf][kk][ty * 8 + 4];
            *(float4*)&b[0] = *(const float4*)&Bs[buf][kk][tx * 8];
            *(float4*)&b[4] = *(const float4*)&Bs[buf][kk][tx * 8 + 4];
            #pragma unroll
            for (int i = 0; i < 8; i++)
                #pragma unroll
                for (int j = 0; j < 8; j++)
                    acc[i][j] = fmaf(a[i], b[j], acc[i][j]);
        }
        __syncthreads();
        buf ^= 1;
    }

    // ---- epilogue: per-row sum of exp over this 128-col slab ----
    #pragma unroll
    for (int i = 0; i < 8; i++) {
        float s = 0.0f;
        #pragma unroll
        for (int j = 0; j < 8; j++) s += __expf(acc[i][j]);
        // reduce across the 16 tx lanes (half-warp butterfly)
        #pragma unroll
        for (int o = 8; o; o >>= 1) s += __shfl_xor_sync(0xffffffffu, s, o, 16);
        if (tx == 0) atomicAdd(&g_rowsum[rowTile + ty * 8 + i], s);
    }
}

// ---------------------------------------------------------------------------
// Kernel 5: loss = mean( log(rowsum - exp(pos)) - pos )
// single block, 1024 threads
// ---------------------------------------------------------------------------
__global__ void loss_kernel(float* __restrict__ out) {
    float acc = 0.0f;
    for (int i = threadIdx.x; i < B_TOT; i += 1024) {
        float p = g_pos[i];
        acc += logf(g_rowsum[i] - expf(p)) - p;
    }
    __shared__ float sh[32];
    int lane = threadIdx.x & 31, w = threadIdx.x >> 5;
    #pragma unroll
    for (int o = 16; o; o >>= 1) acc += __shfl_xor_sync(0xffffffffu, acc, o);
    if (lane == 0) sh[w] = acc;
    __syncthreads();
    if (w == 0) {
        acc = sh[lane];
        #pragma unroll
        for (int o = 16; o; o >>= 1) acc += __shfl_xor_sync(0xffffffffu, acc, o);
        if (lane == 0) out[0] = acc * (1.0f / B_TOT);
    }
}

// ---------------------------------------------------------------------------
extern "C" void kernel_launch(void* const* d_in, const int* in_sizes, int n_in,
                              void* d_out, int out_size) {
    const float* emb = (const float*)d_in[0];
    float* out = (float*)d_out;

    centroid_kernel<<<S_CLS, 256>>>(emb);
    normalize_kernel<<<B_TOT, 256>>>(emb);
    pos_kernel<<<B_TOT, 256>>>();
    dim3 grid(B_TOT / BM, S_CLS / BN);
    gemm_exp_kernel<<<grid, 256>>>();
    loss_kernel<<<1, 1024>>>(out);
}

// round 3
// speedup vs baseline: 7.2664x; 7.2664x over previous
#include <cuda_runtime.h>
#include <cuda_bf16.h>
#include <cstdint>
#include <math.h>

// Problem constants (fixed by setup_inputs: S=2048, U=10, D=256)
#define B_TOT 20480
#define D_DIM 256
#define S_CLS 2048
#define U_UTT 10
#define EPSF  1e-8f

// Scratch (static __device__ arrays: allocation-free per harness rules)
__device__ __nv_bfloat16 g_Enh[(size_t)B_TOT * D_DIM];  // normalized embeddings bf16, 10 MB
__device__ __nv_bfloat16 g_Cnh[(size_t)S_CLS * D_DIM];  // normalized centroids bf16, 1 MB
__device__ float g_Cn[(size_t)S_CLS * D_DIM];           // normalized centroids fp32 (for pos)
__device__ float g_rowsum[B_TOT];                       // sum_k exp(sim[row,k])
__device__ float g_pos[B_TOT];                          // sim[row, label(row)] in fp32

// ===========================================================================
// helpers
// ===========================================================================
__device__ __forceinline__ uint32_t smem_to_u32(const void* p) {
    uint32_t a;
    asm("{ .reg .u64 t; cvta.to.shared.u64 t, %1; cvt.u32.u64 %0, t; }"
        : "=r"(a) : "l"(p));
    return a;
}
__device__ __forceinline__ void cp16(uint32_t dst, const void* src) {
    asm volatile("cp.async.cg.shared.global [%0], [%1], 16;"
                 :: "r"(dst), "l"(src) : "memory");
}
__device__ __forceinline__ float warpSum(float v) {
    #pragma unroll
    for (int o = 16; o; o >>= 1) v += __shfl_xor_sync(0xffffffffu, v, o);
    return v;
}
__device__ __forceinline__ float dot4(float4 a, float4 b) {
    return a.x*b.x + a.y*b.y + a.z*b.z + a.w*b.w;
}
__device__ __forceinline__ uint32_t pack_bf16x2(float lo, float hi) {
    __nv_bfloat162 p = __float22bfloat162_rn(make_float2(lo, hi));
    return *reinterpret_cast<uint32_t*>(&p);
}

// ---------------------------------------------------------------------------
// Kernel 1: centroid per speaker: mean over U, L2-normalize.
// Writes fp32 g_Cn (for pos) and bf16 g_Cnh (for GEMM). Warp per speaker.
// ---------------------------------------------------------------------------
__global__ void centroid_kernel(const float* __restrict__ emb) {
    int s    = blockIdx.x * 8 + (threadIdx.x >> 5);
    int lane = threadIdx.x & 31;
    float4 a = make_float4(0.f, 0.f, 0.f, 0.f);
    float4 b = a;
    const float4* base = (const float4*)(emb + (size_t)s * U_UTT * D_DIM);
    #pragma unroll
    for (int u = 0; u < U_UTT; u++) {
        float4 x = base[u * 64 + lane];
        float4 y = base[u * 64 + lane + 32];
        a.x += x.x; a.y += x.y; a.z += x.z; a.w += x.w;
        b.x += y.x; b.y += y.y; b.z += y.z; b.w += y.w;
    }
    const float inv = 1.0f / U_UTT;
    a.x *= inv; a.y *= inv; a.z *= inv; a.w *= inv;
    b.x *= inv; b.y *= inv; b.z *= inv; b.w *= inv;
    float sq = warpSum(dot4(a, a) + dot4(b, b));
    float sc = 1.0f / fmaxf(sqrtf(sq), EPSF);
    a.x *= sc; a.y *= sc; a.z *= sc; a.w *= sc;
    b.x *= sc; b.y *= sc; b.z *= sc; b.w *= sc;
    float4* outf = (float4*)(g_Cn + (size_t)s * D_DIM);
    outf[lane]      = a;
    outf[lane + 32] = b;
    uint2* outh = (uint2*)(g_Cnh + (size_t)s * D_DIM);
    outh[lane]      = make_uint2(pack_bf16x2(a.x, a.y), pack_bf16x2(a.z, a.w));
    outh[lane + 32] = make_uint2(pack_bf16x2(b.x, b.y), pack_bf16x2(b.z, b.w));
}

// ---------------------------------------------------------------------------
// Kernel 2: row L2-normalize -> g_Enh (bf16); pos[row] in fp32; zero rowsum.
// Warp per row. Must run after centroid_kernel.
// ---------------------------------------------------------------------------
__global__ void norm_pos_kernel(const float* __restrict__ emb) {
    int row  = blockIdx.x * 8 + (threadIdx.x >> 5);
    int lane = threadIdx.x & 31;
    const float4* p = (const float4*)(emb + (size_t)row * D_DIM);
    float4 a = p[lane], b = p[lane + 32];
    float sq = warpSum(dot4(a, a) + dot4(b, b));
    float sc = 1.0f / fmaxf(sqrtf(sq), EPSF);
    a.x *= sc; a.y *= sc; a.z *= sc; a.w *= sc;
    b.x *= sc; b.y *= sc; b.z *= sc; b.w *= sc;
    uint2* outh = (uint2*)(g_Enh + (size_t)row * D_DIM);
    outh[lane]      = make_uint2(pack_bf16x2(a.x, a.y), pack_bf16x2(a.z, a.w));
    outh[lane + 32] = make_uint2(pack_bf16x2(b.x, b.y), pack_bf16x2(b.z, b.w));
    // pos = dot(normalized row, Cn[row/U]) in fp32
    int spk = row / U_UTT;
    const float4* pc = (const float4*)(g_Cn + (size_t)spk * D_DIM);
    float v = dot4(a, pc[lane]) + dot4(b, pc[lane + 32]);
    v = warpSum(v);
    if (lane == 0) {
        g_pos[row] = v;
        g_rowsum[row] = 0.0f;
    }
}

// ---------------------------------------------------------------------------
// Kernel 3: bf16 mma.sync GEMM (En @ Cn^T) 128x128 tile, BK=64, cp.async
// double buffer, fused exp + rowsum epilogue (register accumulators).
// 8 warps in 2x4 grid; each warp: 64 rows x 32 cols = 4x4 m16n8k16 tiles.
// smem: buf b at b*32768: A tile 128x64 bf16 (16KB) + B tile (16KB).
// Swizzle: 128B rows -> off ^ ((row&7)<<4).
// ---------------------------------------------------------------------------
#define GEMM_SMEM 65536

__global__ __launch_bounds__(256, 2)
void gemm_bf16_kernel() {
    extern __shared__ char smem[];
    const uint32_t sb = smem_to_u32(smem);
    const int tid  = threadIdx.x;
    const int lane = tid & 31;
    const int wid  = tid >> 5;
    const int rowTile = blockIdx.x * 128;
    const int colTile = blockIdx.y * 128;
    const int rowBase = (wid >> 2) * 64;   // warp row  (0 or 64)
    const int colBase = (wid & 3) * 32;    // warp col  (0,32,64,96)

    // loader mapping: 512 x 16B per operand tile; thread does 4 A + 4 B loads
    const int lrow = tid >> 3;   // 0..31 ; rows lrow + 32*j
    const int lseg = tid & 7;    // 16B segment within 128B row

    float acc[4][4][4];
    #pragma unroll
    for (int mi = 0; mi < 4; mi++)
        #pragma unroll
        for (int ni = 0; ni < 4; ni++)
            #pragma unroll
            for (int q = 0; q < 4; q++) acc[mi][ni][q] = 0.0f;

    auto load_chunk = [&](int c, int buf) {
        #pragma unroll
        for (int j = 0; j < 4; j++) {
            int row = lrow + 32 * j;
            uint32_t dst = sb + buf * 32768 + row * 128
                         + ((lseg * 16) ^ ((row & 7) << 4));
            cp16(dst,
                 g_Enh + (size_t)(rowTile + row) * D_DIM + c * 64 + lseg * 8);
            cp16(dst + 16384,
                 g_Cnh + (size_t)(colTile + row) * D_DIM + c * 64 + lseg * 8);
        }
        asm volatile("cp.async.commit_group;" ::: "memory");
    };

    load_chunk(0, 0);
    load_chunk(1, 1);

    #pragma unroll
    for (int c = 0; c < 4; c++) {
        const int buf = c & 1;
        if (c < 3) asm volatile("cp.async.wait_group 1;" ::: "memory");
        else       asm volatile("cp.async.wait_group 0;" ::: "memory");
        __syncthreads();

        const uint32_t aB = sb + buf * 32768;
        const uint32_t bB = aB + 16384;

        #pragma unroll
        for (int ks = 0; ks < 4; ks++) {
            uint32_t a[4][4];
            uint32_t b[4][2];
            #pragma unroll
            for (int mi = 0; mi < 4; mi++) {
                int r = rowBase + mi * 16 + (lane & 15);
                uint32_t addr = aB + r * 128
                    + ((ks * 32 + (lane >> 4) * 16) ^ ((r & 7) << 4));
                asm volatile(
                    "ldmatrix.sync.aligned.m8n8.x4.shared.b16 {%0,%1,%2,%3}, [%4];"
                    : "=r"(a[mi][0]), "=r"(a[mi][1]), "=r"(a[mi][2]), "=r"(a[mi][3])
                    : "r"(addr));
            }
            #pragma unroll
            for (int ni = 0; ni < 4; ni++) {
                int r = colBase + ni * 8 + (lane & 7);
                uint32_t addr = bB + r * 128
                    + ((ks * 32 + ((lane >> 3) & 1) * 16) ^ ((r & 7) << 4));
                asm volatile(
                    "ldmatrix.sync.aligned.m8n8.x2.shared.b16 {%0,%1}, [%2];"
                    : "=r"(b[ni][0]), "=r"(b[ni][1])
                    : "r"(addr));
            }
            #pragma unroll
            for (int mi = 0; mi < 4; mi++)
                #pragma unroll
                for (int ni = 0; ni < 4; ni++) {
                    asm volatile(
                        "mma.sync.aligned.m16n8k16.row.col.f32.bf16.bf16.f32 "
                        "{%0,%1,%2,%3}, {%4,%5,%6,%7}, {%8,%9}, {%0,%1,%2,%3};"
                        : "+f"(acc[mi][ni][0]), "+f"(acc[mi][ni][1]),
                          "+f"(acc[mi][ni][2]), "+f"(acc[mi][ni][3])
                        : "r"(a[mi][0]), "r"(a[mi][1]), "r"(a[mi][2]), "r"(a[mi][3]),
                          "r"(b[ni][0]), "r"(b[ni][1]));
                }
        }
        __syncthreads();
        if (c + 2 < 4) load_chunk(c + 2, buf);
    }

    // epilogue: acc[mi][ni] quad q: rows g / g+8, col pairs tg*2, tg*2+1
    const int g  = lane >> 2;
    const int tg = lane & 3;
    #pragma unroll
    for (int mi = 0; mi < 4; mi++) {
        float s0 = 0.0f, s1 = 0.0f;
        #pragma unroll
        for (int ni = 0; ni < 4; ni++) {
            s0 += __expf(acc[mi][ni][0]) + __expf(acc[mi][ni][1]);
            s1 += __expf(acc[mi][ni][2]) + __expf(acc[mi][ni][3]);
        }
        s0 += __shfl_xor_sync(0xffffffffu, s0, 1);
        s0 += __shfl_xor_sync(0xffffffffu, s0, 2);
        s1 += __shfl_xor_sync(0xffffffffu, s1, 1);
        s1 += __shfl_xor_sync(0xffffffffu, s1, 2);
        if (tg == 0) {
            int r = rowTile + rowBase + mi * 16 + g;
            atomicAdd(&g_rowsum[r],     s0);
            atomicAdd(&g_rowsum[r + 8], s1);
        }
    }
}

// ---------------------------------------------------------------------------
// Kernel 4: loss = mean( log(rowsum - exp(pos)) - pos )
// ---------------------------------------------------------------------------
__global__ void loss_kernel(float* __restrict__ out) {
    float acc = 0.0f;
    for (int i = threadIdx.x; i < B_TOT; i += 1024) {
        float p = g_pos[i];
        acc += logf(g_rowsum[i] - expf(p)) - p;
    }
    __shared__ float sh[32];
    int lane = threadIdx.x & 31, w = threadIdx.x >> 5;
    acc = warpSum(acc);
    if (lane == 0) sh[w] = acc;
    __syncthreads();
    if (w == 0) {
        acc = sh[lane];
        acc = warpSum(acc);
        if (lane == 0) out[0] = acc * (1.0f / B_TOT);
    }
}

// ---------------------------------------------------------------------------
extern "C" void kernel_launch(void* const* d_in, const int* in_sizes, int n_in,
                              void* d_out, int out_size) {
    const float* emb = (const float*)d_in[0];
    float* out = (float*)d_out;

    cudaFuncSetAttribute(gemm_bf16_kernel,
                         cudaFuncAttributeMaxDynamicSharedMemorySize,
                         GEMM_SMEM);

    centroid_kernel<<<S_CLS / 8, 256>>>(emb);
    norm_pos_kernel<<<B_TOT / 8, 256>>>(emb);
    dim3 grid(B_TOT / 128, S_CLS / 128);
    gemm_bf16_kernel<<<grid, 256, GEMM_SMEM>>>();
    loss_kernel<<<1, 1024>>>(out);
}

// round 4
// speedup vs baseline: 7.6561x; 1.0536x over previous
#include <cuda_runtime.h>
#include <cuda_bf16.h>
#include <cstdint>
#include <math.h>

// Problem constants (fixed by setup_inputs: S=2048, U=10, D=256)
#define B_TOT 20480
#define D_DIM 256
#define S_CLS 2048
#define U_UTT 10
#define EPSF  1e-8f

// Scratch (static __device__ arrays: allocation-free per harness rules)
__device__ __nv_bfloat16 g_Enh[(size_t)B_TOT * D_DIM];  // normalized embeddings bf16, 10 MB
__device__ __nv_bfloat16 g_Cnh[(size_t)S_CLS * D_DIM];  // normalized centroids bf16, 1 MB
__device__ float g_Cn[(size_t)S_CLS * D_DIM];           // normalized centroids fp32 (for pos)
__device__ float g_rowsum[B_TOT];                       // sum_k exp(sim[row,k])
__device__ float g_pos[B_TOT];                          // sim[row, label(row)] in fp32

// ===========================================================================
// helpers
// ===========================================================================
__device__ __forceinline__ uint32_t smem_to_u32(const void* p) {
    uint32_t a;
    asm("{ .reg .u64 t; cvta.to.shared.u64 t, %1; cvt.u32.u64 %0, t; }"
        : "=r"(a) : "l"(p));
    return a;
}
__device__ __forceinline__ void cp16(uint32_t dst, const void* src) {
    asm volatile("cp.async.cg.shared.global [%0], [%1], 16;"
                 :: "r"(dst), "l"(src) : "memory");
}
__device__ __forceinline__ float warpSum(float v) {
    #pragma unroll
    for (int o = 16; o; o >>= 1) v += __shfl_xor_sync(0xffffffffu, v, o);
    return v;
}
__device__ __forceinline__ float dot4(float4 a, float4 b) {
    return a.x*b.x + a.y*b.y + a.z*b.z + a.w*b.w;
}
__device__ __forceinline__ uint32_t pack_bf16x2(float lo, float hi) {
    __nv_bfloat162 p = __float22bfloat162_rn(make_float2(lo, hi));
    return *reinterpret_cast<uint32_t*>(&p);
}

// ---------------------------------------------------------------------------
// Kernel 1: centroid per speaker: mean over U, L2-normalize.
// Writes fp32 g_Cn (for pos) and bf16 g_Cnh (for GEMM). Warp per speaker.
// Also zeroes out[0] (loss accumulator) once per graph replay.
// ---------------------------------------------------------------------------
__global__ void centroid_kernel(const float* __restrict__ emb,
                                float* __restrict__ out) {
    if (blockIdx.x == 0 && threadIdx.x == 0) out[0] = 0.0f;
    int s    = blockIdx.x * 8 + (threadIdx.x >> 5);
    int lane = threadIdx.x & 31;
    float4 a = make_float4(0.f, 0.f, 0.f, 0.f);
    float4 b = a;
    const float4* base = (const float4*)(emb + (size_t)s * U_UTT * D_DIM);
    #pragma unroll
    for (int u = 0; u < U_UTT; u++) {
        float4 x = base[u * 64 + lane];
        float4 y = base[u * 64 + lane + 32];
        a.x += x.x; a.y += x.y; a.z += x.z; a.w += x.w;
        b.x += y.x; b.y += y.y; b.z += y.z; b.w += y.w;
    }
    const float inv = 1.0f / U_UTT;
    a.x *= inv; a.y *= inv; a.z *= inv; a.w *= inv;
    b.x *= inv; b.y *= inv; b.z *= inv; b.w *= inv;
    float sq = warpSum(dot4(a, a) + dot4(b, b));
    float sc = 1.0f / fmaxf(sqrtf(sq), EPSF);
    a.x *= sc; a.y *= sc; a.z *= sc; a.w *= sc;
    b.x *= sc; b.y *= sc; b.z *= sc; b.w *= sc;
    float4* outf = (float4*)(g_Cn + (size_t)s * D_DIM);
    outf[lane]      = a;
    outf[lane + 32] = b;
    uint2* outh = (uint2*)(g_Cnh + (size_t)s * D_DIM);
    outh[lane]      = make_uint2(pack_bf16x2(a.x, a.y), pack_bf16x2(a.z, a.w));
    outh[lane + 32] = make_uint2(pack_bf16x2(b.x, b.y), pack_bf16x2(b.z, b.w));
}

// ---------------------------------------------------------------------------
// Kernel 2: row L2-normalize -> g_Enh (bf16); pos[row] in fp32; zero rowsum.
// Warp per row. Must run after centroid_kernel.
// ---------------------------------------------------------------------------
__global__ void norm_pos_kernel(const float* __restrict__ emb) {
    int row  = blockIdx.x * 8 + (threadIdx.x >> 5);
    int lane = threadIdx.x & 31;
    const float4* p = (const float4*)(emb + (size_t)row * D_DIM);
    float4 a = p[lane], b = p[lane + 32];
    float sq = warpSum(dot4(a, a) + dot4(b, b));
    float sc = 1.0f / fmaxf(sqrtf(sq), EPSF);
    a.x *= sc; a.y *= sc; a.z *= sc; a.w *= sc;
    b.x *= sc; b.y *= sc; b.z *= sc; b.w *= sc;
    uint2* outh = (uint2*)(g_Enh + (size_t)row * D_DIM);
    outh[lane]      = make_uint2(pack_bf16x2(a.x, a.y), pack_bf16x2(a.z, a.w));
    outh[lane + 32] = make_uint2(pack_bf16x2(b.x, b.y), pack_bf16x2(b.z, b.w));
    // pos = dot(normalized row, Cn[row/U]) in fp32
    int spk = row / U_UTT;
    const float4* pc = (const float4*)(g_Cn + (size_t)spk * D_DIM);
    float v = dot4(a, pc[lane]) + dot4(b, pc[lane + 32]);
    v = warpSum(v);
    if (lane == 0) {
        g_pos[row] = v;
        g_rowsum[row] = 0.0f;
    }
}

// ---------------------------------------------------------------------------
// Kernel 3: bf16 mma.sync GEMM (En @ Cn^T) 128x128 tile, BK=64, cp.async
// double buffer, fused exp + rowsum epilogue (register accumulators).
// 8 warps in 2x4 grid; each warp: 64 rows x 32 cols = 4x4 m16n8k16 tiles.
// smem: buf b at b*32768: A tile 128x64 bf16 (16KB) + B tile (16KB).
// Swizzle: 128B rows -> off ^ ((row&7)<<4).
// ---------------------------------------------------------------------------
#define GEMM_SMEM 65536

__global__ __launch_bounds__(256, 2)
void gemm_bf16_kernel() {
    extern __shared__ char smem[];
    const uint32_t sb = smem_to_u32(smem);
    const int tid  = threadIdx.x;
    const int lane = tid & 31;
    const int wid  = tid >> 5;
    const int rowTile = blockIdx.x * 128;
    const int colTile = blockIdx.y * 128;
    const int rowBase = (wid >> 2) * 64;   // warp row  (0 or 64)
    const int colBase = (wid & 3) * 32;    // warp col  (0,32,64,96)

    // loader mapping: 512 x 16B per operand tile; thread does 4 A + 4 B loads
    const int lrow = tid >> 3;   // 0..31 ; rows lrow + 32*j
    const int lseg = tid & 7;    // 16B segment within 128B row

    float acc[4][4][4];
    #pragma unroll
    for (int mi = 0; mi < 4; mi++)
        #pragma unroll
        for (int ni = 0; ni < 4; ni++)
            #pragma unroll
            for (int q = 0; q < 4; q++) acc[mi][ni][q] = 0.0f;

    auto load_chunk = [&](int c, int buf) {
        #pragma unroll
        for (int j = 0; j < 4; j++) {
            int row = lrow + 32 * j;
            uint32_t dst = sb + buf * 32768 + row * 128
                         + ((lseg * 16) ^ ((row & 7) << 4));
            cp16(dst,
                 g_Enh + (size_t)(rowTile + row) * D_DIM + c * 64 + lseg * 8);
            cp16(dst + 16384,
                 g_Cnh + (size_t)(colTile + row) * D_DIM + c * 64 + lseg * 8);
        }
        asm volatile("cp.async.commit_group;" ::: "memory");
    };

    load_chunk(0, 0);
    load_chunk(1, 1);

    #pragma unroll
    for (int c = 0; c < 4; c++) {
        const int buf = c & 1;
        if (c < 3) asm volatile("cp.async.wait_group 1;" ::: "memory");
        else       asm volatile("cp.async.wait_group 0;" ::: "memory");
        __syncthreads();

        const uint32_t aB = sb + buf * 32768;
        const uint32_t bB = aB + 16384;

        #pragma unroll
        for (int ks = 0; ks < 4; ks++) {
            uint32_t a[4][4];
            uint32_t b[4][2];
            #pragma unroll
            for (int mi = 0; mi < 4; mi++) {
                int r = rowBase + mi * 16 + (lane & 15);
                uint32_t addr = aB + r * 128
                    + ((ks * 32 + (lane >> 4) * 16) ^ ((r & 7) << 4));
                asm volatile(
                    "ldmatrix.sync.aligned.m8n8.x4.shared.b16 {%0,%1,%2,%3}, [%4];"
                    : "=r"(a[mi][0]), "=r"(a[mi][1]), "=r"(a[mi][2]), "=r"(a[mi][3])
                    : "r"(addr));
            }
            #pragma unroll
            for (int ni = 0; ni < 4; ni++) {
                int r = colBase + ni * 8 + (lane & 7);
                uint32_t addr = bB + r * 128
                    + ((ks * 32 + ((lane >> 3) & 1) * 16) ^ ((r & 7) << 4));
                asm volatile(
                    "ldmatrix.sync.aligned.m8n8.x2.shared.b16 {%0,%1}, [%2];"
                    : "=r"(b[ni][0]), "=r"(b[ni][1])
                    : "r"(addr));
            }
            #pragma unroll
            for (int mi = 0; mi < 4; mi++)
                #pragma unroll
                for (int ni = 0; ni < 4; ni++) {
                    asm volatile(
                        "mma.sync.aligned.m16n8k16.row.col.f32.bf16.bf16.f32 "
                        "{%0,%1,%2,%3}, {%4,%5,%6,%7}, {%8,%9}, {%0,%1,%2,%3};"
                        : "+f"(acc[mi][ni][0]), "+f"(acc[mi][ni][1]),
                          "+f"(acc[mi][ni][2]), "+f"(acc[mi][ni][3])
                        : "r"(a[mi][0]), "r"(a[mi][1]), "r"(a[mi][2]), "r"(a[mi][3]),
                          "r"(b[ni][0]), "r"(b[ni][1]));
                }
        }
        __syncthreads();
        if (c + 2 < 4) load_chunk(c + 2, buf);
    }

    // epilogue: acc[mi][ni] quad q: rows g / g+8, col pairs tg*2, tg*2+1
    const int g  = lane >> 2;
    const int tg = lane & 3;
    #pragma unroll
    for (int mi = 0; mi < 4; mi++) {
        float s0 = 0.0f, s1 = 0.0f;
        #pragma unroll
        for (int ni = 0; ni < 4; ni++) {
            s0 += __expf(acc[mi][ni][0]) + __expf(acc[mi][ni][1]);
            s1 += __expf(acc[mi][ni][2]) + __expf(acc[mi][ni][3]);
        }
        s0 += __shfl_xor_sync(0xffffffffu, s0, 1);
        s0 += __shfl_xor_sync(0xffffffffu, s0, 2);
        s1 += __shfl_xor_sync(0xffffffffu, s1, 1);
        s1 += __shfl_xor_sync(0xffffffffu, s1, 2);
        if (tg == 0) {
            int r = rowTile + rowBase + mi * 16 + g;
            atomicAdd(&g_rowsum[r],     s0);
            atomicAdd(&g_rowsum[r + 8], s1);
        }
    }
}

// ---------------------------------------------------------------------------
// Kernel 4: loss partials -> atomicAdd into out[0].
// grid = 80 blocks x 256 threads, one row per thread.
// out[0] is zeroed by centroid_kernel at the head of the same graph replay.
// ---------------------------------------------------------------------------
__global__ void loss_kernel(float* __restrict__ out) {
    int i = blockIdx.x * 256 + threadIdx.x;
    float p = g_pos[i];
    float acc = logf(g_rowsum[i] - expf(p)) - p;
    __shared__ float sh[8];
    int lane = threadIdx.x & 31, w = threadIdx.x >> 5;
    acc = warpSum(acc);
    if (lane == 0) sh[w] = acc;
    __syncthreads();
    if (w == 0) {
        acc = (lane < 8) ? sh[lane] : 0.0f;
        #pragma unroll
        for (int o = 4; o; o >>= 1) acc += __shfl_xor_sync(0xffffffffu, acc, o);
        if (lane == 0) atomicAdd(out, acc * (1.0f / B_TOT));
    }
}

// ---------------------------------------------------------------------------
extern "C" void kernel_launch(void* const* d_in, const int* in_sizes, int n_in,
                              void* d_out, int out_size) {
    const float* emb = (const float*)d_in[0];
    float* out = (float*)d_out;

    cudaFuncSetAttribute(gemm_bf16_kernel,
                         cudaFuncAttributeMaxDynamicSharedMemorySize,
                         GEMM_SMEM);

    centroid_kernel<<<S_CLS / 8, 256>>>(emb, out);
    norm_pos_kernel<<<B_TOT / 8, 256>>>(emb);
    dim3 grid(B_TOT / 128, S_CLS / 128);
    gemm_bf16_kernel<<<grid, 256, GEMM_SMEM>>>();
    loss_kernel<<<B_TOT / 256, 256>>>(out);
}